// round 1
// baseline (speedup 1.0000x reference)
#include <cuda_runtime.h>
#include <math.h>

#define NROW 8192
#define DIM  256

// Scratch (no cudaMalloc allowed): normalized+scaled embeddings and the W/T matrix.
static __device__ float g_embn[(size_t)NROW * DIM];            // 8 MB
static __device__ float g_W[(size_t)NROW * NROW];              // 256 MB

// ---------------------------------------------------------------------------
// K1: row L2-normalize, fold in 1/sqrt(sigma) so W = dot(embn_i, embn_j).
// One warp per row, 4 rows per 128-thread block.
// ---------------------------------------------------------------------------
__global__ void k_normalize(const float* __restrict__ emb)
{
    int row  = blockIdx.x * 4 + (threadIdx.x >> 5);
    int lane = threadIdx.x & 31;
    const float4* src = (const float4*)(emb + (size_t)row * DIM);
    float4 v0 = src[lane];
    float4 v1 = src[lane + 32];
    float s = v0.x*v0.x + v0.y*v0.y + v0.z*v0.z + v0.w*v0.w
            + v1.x*v1.x + v1.y*v1.y + v1.z*v1.z + v1.w*v1.w;
    #pragma unroll
    for (int o = 16; o; o >>= 1) s += __shfl_xor_sync(0xFFFFFFFFu, s, o);
    float nrm = fmaxf(sqrtf(s), 1e-12f);
    // 1/(norm * sqrt(sigma)); sqrt(0.1) = 0.31622776601683794
    float scale = 1.0f / (nrm * 0.316227766016838f);
    float4* dst = (float4*)(g_embn + (size_t)row * DIM);
    v0.x *= scale; v0.y *= scale; v0.z *= scale; v0.w *= scale;
    v1.x *= scale; v1.y *= scale; v1.z *= scale; v1.w *= scale;
    dst[lane]      = v0;
    dst[lane + 32] = v1;
}

// ---------------------------------------------------------------------------
// K2: W = embn @ embn^T  (NT GEMM, M=N=8192, K=256).
// 128x128x16 tiles, 256 threads, 8x8 per thread. Smem k-major, stride 136
// (bank-conflict-free transposed stores, 16B-aligned rows: 136*4 = 544 = 34*16).
// ---------------------------------------------------------------------------
__global__ __launch_bounds__(256, 2) void k_gemm_s()
{
    __shared__ float As[16][136];
    __shared__ float Bs[16][136];

    const float* A = g_embn;
    int tid = threadIdx.x;
    int bm0 = blockIdx.y * 128;
    int bn0 = blockIdx.x * 128;
    int ty = tid >> 4;      // 0..15
    int tx = tid & 15;      // 0..15

    float acc[8][8];
    #pragma unroll
    for (int i = 0; i < 8; i++)
        #pragma unroll
        for (int j = 0; j < 8; j++) acc[i][j] = 0.0f;

    for (int kt = 0; kt < DIM; kt += 16) {
        #pragma unroll
        for (int q = 0; q < 2; q++) {
            int v   = tid + q * 256;
            int row = v >> 2;
            int kg  = (v & 3) * 4;
            float4 a = *(const float4*)(A + (size_t)(bm0 + row) * DIM + kt + kg);
            As[kg + 0][row] = a.x; As[kg + 1][row] = a.y;
            As[kg + 2][row] = a.z; As[kg + 3][row] = a.w;
            float4 b = *(const float4*)(A + (size_t)(bn0 + row) * DIM + kt + kg);
            Bs[kg + 0][row] = b.x; Bs[kg + 1][row] = b.y;
            Bs[kg + 2][row] = b.z; Bs[kg + 3][row] = b.w;
        }
        __syncthreads();
        #pragma unroll
        for (int k = 0; k < 16; k++) {
            float a[8], b[8];
            *(float4*)(a)     = *(float4*)&As[k][ty * 4];
            *(float4*)(a + 4) = *(float4*)&As[k][ty * 4 + 64];
            *(float4*)(b)     = *(float4*)&Bs[k][tx * 4];
            *(float4*)(b + 4) = *(float4*)&Bs[k][tx * 4 + 64];
            #pragma unroll
            for (int i = 0; i < 8; i++)
                #pragma unroll
                for (int j = 0; j < 8; j++)
                    acc[i][j] += a[i] * b[j];
        }
        __syncthreads();
    }

    #pragma unroll
    for (int i = 0; i < 8; i++) {
        int r = bm0 + ty * 4 + ((i < 4) ? i : (64 + i - 4));
        float4 c0 = make_float4(acc[i][0], acc[i][1], acc[i][2], acc[i][3]);
        float4 c1 = make_float4(acc[i][4], acc[i][5], acc[i][6], acc[i][7]);
        *(float4*)(g_W + (size_t)r * NROW + bn0 + tx * 4)      = c0;
        *(float4*)(g_W + (size_t)r * NROW + bn0 + tx * 4 + 64) = c1;
    }
}

// ---------------------------------------------------------------------------
// Fast exp: FFMA-pipe polynomial (avoids MUFU.EX2 throughput wall at 67M exps).
// exp(x) = 2^(x*log2e); 2^f via degree-6 Taylor (rel err ~8e-6), scale via bits.
// ---------------------------------------------------------------------------
__device__ __forceinline__ float fast_exp(float x)
{
    float t = x * 1.4426950408889634f;
    t = fmaxf(t, -126.0f);
    float fi = floorf(t);
    float f  = t - fi;
    float p = 1.5403530393381608e-4f;
    p = fmaf(p, f, 1.3333558146428443e-3f);
    p = fmaf(p, f, 9.6181291076284770e-3f);
    p = fmaf(p, f, 5.5504108664821580e-2f);
    p = fmaf(p, f, 2.4022650695910070e-1f);
    p = fmaf(p, f, 6.9314718055994530e-1f);
    p = fmaf(p, f, 1.0f);
    int ei = (int)fi;
    return p * __int_as_float((ei + 127) << 23);
}

// ---------------------------------------------------------------------------
// K3: in-place row softmax on g_W. One block per row; 32 elements/thread held
// in registers (single read + single write of the 256 MB matrix).
// ---------------------------------------------------------------------------
__global__ __launch_bounds__(256) void k_softmax()
{
    size_t row = blockIdx.x;
    float* w = g_W + row * (size_t)NROW;
    int tid = threadIdx.x;
    __shared__ float red[8];

    float4 v[8];
    #pragma unroll
    for (int i = 0; i < 8; i++) v[i] = ((float4*)w)[tid + i * 256];

    float m = -3.402823466e38f;
    #pragma unroll
    for (int i = 0; i < 8; i++) {
        m = fmaxf(m, fmaxf(fmaxf(v[i].x, v[i].y), fmaxf(v[i].z, v[i].w)));
    }
    #pragma unroll
    for (int o = 16; o; o >>= 1) m = fmaxf(m, __shfl_xor_sync(0xFFFFFFFFu, m, o));
    if ((tid & 31) == 0) red[tid >> 5] = m;
    __syncthreads();
    if (tid < 8) {
        float t = red[tid];
        #pragma unroll
        for (int o = 4; o; o >>= 1) t = fmaxf(t, __shfl_xor_sync(0xFFu, t, o));
        if (tid == 0) red[0] = t;
    }
    __syncthreads();
    m = red[0];
    __syncthreads();

    float s = 0.0f;
    #pragma unroll
    for (int i = 0; i < 8; i++) {
        v[i].x = fast_exp(v[i].x - m); v[i].y = fast_exp(v[i].y - m);
        v[i].z = fast_exp(v[i].z - m); v[i].w = fast_exp(v[i].w - m);
        s += (v[i].x + v[i].y) + (v[i].z + v[i].w);
    }
    #pragma unroll
    for (int o = 16; o; o >>= 1) s += __shfl_xor_sync(0xFFFFFFFFu, s, o);
    if ((tid & 31) == 0) red[tid >> 5] = s;
    __syncthreads();
    if (tid < 8) {
        float t = red[tid];
        #pragma unroll
        for (int o = 4; o; o >>= 1) t += __shfl_xor_sync(0xFFu, t, o);
        if (tid == 0) red[0] = t;
    }
    __syncthreads();
    float inv = 1.0f / red[0];

    #pragma unroll
    for (int i = 0; i < 8; i++) {
        v[i].x *= inv; v[i].y *= inv; v[i].z *= inv; v[i].w *= inv;
        ((float4*)w)[tid + i * 256] = v[i];
    }
}

// ---------------------------------------------------------------------------
// K4: out = T @ emb_org  (NN GEMM, M=8192, N=256, K=8192).
// Same 128x128x16 tiling; B tile is already k-major in memory.
// ---------------------------------------------------------------------------
__global__ __launch_bounds__(256, 2) void k_gemm_o(const float* __restrict__ B,
                                                   float* __restrict__ C)
{
    __shared__ float As[16][136];
    __shared__ float Bs[16][136];

    const float* A = g_W;
    int tid = threadIdx.x;
    int bm0 = blockIdx.y * 128;
    int bn0 = blockIdx.x * 128;
    int ty = tid >> 4;
    int tx = tid & 15;

    float acc[8][8];
    #pragma unroll
    for (int i = 0; i < 8; i++)
        #pragma unroll
        for (int j = 0; j < 8; j++) acc[i][j] = 0.0f;

    for (int kt = 0; kt < NROW; kt += 16) {
        #pragma unroll
        for (int q = 0; q < 2; q++) {
            int v   = tid + q * 256;
            // A tile: transposed store (k-major)
            int row = v >> 2;
            int kg  = (v & 3) * 4;
            float4 a = *(const float4*)(A + (size_t)(bm0 + row) * NROW + kt + kg);
            As[kg + 0][row] = a.x; As[kg + 1][row] = a.y;
            As[kg + 2][row] = a.z; As[kg + 3][row] = a.w;
            // B tile: direct (rows of B are the k dimension)
            int kr = v >> 5;
            int nc = (v & 31) * 4;
            *(float4*)&Bs[kr][nc] =
                *(const float4*)(B + (size_t)(kt + kr) * DIM + bn0 + nc);
        }
        __syncthreads();
        #pragma unroll
        for (int k = 0; k < 16; k++) {
            float a[8], b[8];
            *(float4*)(a)     = *(float4*)&As[k][ty * 4];
            *(float4*)(a + 4) = *(float4*)&As[k][ty * 4 + 64];
            *(float4*)(b)     = *(float4*)&Bs[k][tx * 4];
            *(float4*)(b + 4) = *(float4*)&Bs[k][tx * 4 + 64];
            #pragma unroll
            for (int i = 0; i < 8; i++)
                #pragma unroll
                for (int j = 0; j < 8; j++)
                    acc[i][j] += a[i] * b[j];
        }
        __syncthreads();
    }

    #pragma unroll
    for (int i = 0; i < 8; i++) {
        int r = bm0 + ty * 4 + ((i < 4) ? i : (64 + i - 4));
        float4 c0 = make_float4(acc[i][0], acc[i][1], acc[i][2], acc[i][3]);
        float4 c1 = make_float4(acc[i][4], acc[i][5], acc[i][6], acc[i][7]);
        *(float4*)(C + (size_t)r * DIM + bn0 + tx * 4)      = c0;
        *(float4*)(C + (size_t)r * DIM + bn0 + tx * 4 + 64) = c1;
    }
}

// ---------------------------------------------------------------------------
extern "C" void kernel_launch(void* const* d_in, const int* in_sizes, int n_in,
                              void* d_out, int out_size)
{
    const float* emb = (const float*)d_in[0];
    float* out = (float*)d_out;

    k_normalize<<<NROW / 4, 128>>>(emb);

    dim3 gs(NROW / 128, NROW / 128);         // 64 x 64
    k_gemm_s<<<gs, 256>>>();

    k_softmax<<<NROW, 256>>>();

    dim3 go(DIM / 128, NROW / 128);          // 2 x 64
    k_gemm_o<<<go, 256>>>(emb, out);
}

// round 3
// speedup vs baseline: 2.9129x; 2.9129x over previous
#include <cuda_runtime.h>
#include <cuda_bf16.h>
#include <math.h>
#include <stdint.h>

#define NROW 8192
#define DIM  256

// ---------------- scratch (no cudaMalloc allowed) ----------------
static __device__ float         g_W   [(size_t)NROW * NROW];   // 256 MB
static __device__ __nv_bfloat16 g_Thi [(size_t)NROW * NROW];   // 128 MB
static __device__ __nv_bfloat16 g_Tlo [(size_t)NROW * NROW];   // 128 MB
static __device__ __nv_bfloat16 g_Ehi [(size_t)NROW * DIM];    // 4 MB
static __device__ __nv_bfloat16 g_Elo [(size_t)NROW * DIM];    // 4 MB
static __device__ __nv_bfloat16 g_Vthi[(size_t)DIM * NROW];    // 4 MB
static __device__ __nv_bfloat16 g_Vtlo[(size_t)DIM * NROW];    // 4 MB

// ---------------- portable PTX helpers (sm_80+ features only) ----------------
__device__ __forceinline__ uint32_t smem_u32(const void* p) {
    return (uint32_t)__cvta_generic_to_shared(p);
}
__device__ __forceinline__ void cp16(uint32_t dst, const void* src) {
    asm volatile("cp.async.cg.shared.global [%0], [%1], 16;"
                 :: "r"(dst), "l"(src) : "memory");
}
__device__ __forceinline__ void cp_commit() {
    asm volatile("cp.async.commit_group;" ::: "memory");
}
template <int N> __device__ __forceinline__ void cp_wait() {
    asm volatile("cp.async.wait_group %0;" :: "n"(N) : "memory");
}
__device__ __forceinline__ void ldsm4(uint32_t& r0, uint32_t& r1,
                                      uint32_t& r2, uint32_t& r3, uint32_t addr) {
    asm volatile("ldmatrix.sync.aligned.m8n8.x4.shared.b16 {%0,%1,%2,%3}, [%4];"
                 : "=r"(r0), "=r"(r1), "=r"(r2), "=r"(r3) : "r"(addr));
}
__device__ __forceinline__ void mma16816(float* d,
                                         uint32_t a0, uint32_t a1, uint32_t a2, uint32_t a3,
                                         uint32_t b0, uint32_t b1) {
    asm volatile("mma.sync.aligned.m16n8k16.row.col.f32.bf16.bf16.f32 "
                 "{%0,%1,%2,%3},{%4,%5,%6,%7},{%8,%9},{%0,%1,%2,%3};"
                 : "+f"(d[0]), "+f"(d[1]), "+f"(d[2]), "+f"(d[3])
                 : "r"(a0), "r"(a1), "r"(a2), "r"(a3), "r"(b0), "r"(b1));
}

// ---------------------------------------------------------------------------
// K1: normalize rows (fold 1/sqrt(sigma)), split into bf16 hi/lo.
// ---------------------------------------------------------------------------
__device__ __forceinline__ void split4(__nv_bfloat16* hi, __nv_bfloat16* lo,
                                       size_t idx, float4 v)
{
    __nv_bfloat16 h0 = __float2bfloat16(v.x), h1 = __float2bfloat16(v.y);
    __nv_bfloat16 h2 = __float2bfloat16(v.z), h3 = __float2bfloat16(v.w);
    __nv_bfloat16 l0 = __float2bfloat16(v.x - __bfloat162float(h0));
    __nv_bfloat16 l1 = __float2bfloat16(v.y - __bfloat162float(h1));
    __nv_bfloat16 l2 = __float2bfloat16(v.z - __bfloat162float(h2));
    __nv_bfloat16 l3 = __float2bfloat16(v.w - __bfloat162float(h3));
    *(__nv_bfloat162*)(hi + idx)     = __halves2bfloat162(h0, h1);
    *(__nv_bfloat162*)(hi + idx + 2) = __halves2bfloat162(h2, h3);
    *(__nv_bfloat162*)(lo + idx)     = __halves2bfloat162(l0, l1);
    *(__nv_bfloat162*)(lo + idx + 2) = __halves2bfloat162(l2, l3);
}

__global__ void k_normalize(const float* __restrict__ emb)
{
    int row  = blockIdx.x * 4 + (threadIdx.x >> 5);
    int lane = threadIdx.x & 31;
    const float4* src = (const float4*)(emb + (size_t)row * DIM);
    float4 v0 = src[lane];
    float4 v1 = src[lane + 32];
    float s = v0.x*v0.x + v0.y*v0.y + v0.z*v0.z + v0.w*v0.w
            + v1.x*v1.x + v1.y*v1.y + v1.z*v1.z + v1.w*v1.w;
    #pragma unroll
    for (int o = 16; o; o >>= 1) s += __shfl_xor_sync(0xFFFFFFFFu, s, o);
    float nrm = fmaxf(sqrtf(s), 1e-12f);
    float scale = 1.0f / (nrm * 0.316227766016838f);   // 1/(norm*sqrt(sigma))
    v0.x *= scale; v0.y *= scale; v0.z *= scale; v0.w *= scale;
    v1.x *= scale; v1.y *= scale; v1.z *= scale; v1.w *= scale;
    size_t base = (size_t)row * DIM;
    split4(g_Ehi, g_Elo, base + lane * 4,        v0);
    split4(g_Ehi, g_Elo, base + (lane + 32) * 4, v1);
}

// ---------------------------------------------------------------------------
// K2: tiled transpose + split of V = emb_org -> Vt[c][r] (bf16 hi/lo).
// ---------------------------------------------------------------------------
__global__ void k_transpose_split(const float* __restrict__ emb)
{
    __shared__ float t[32][33];
    int r0 = blockIdx.x * 32;
    int c0 = blockIdx.y * 32;
    int tx = threadIdx.x, ty = threadIdx.y;   // 32 x 8
    #pragma unroll
    for (int i = 0; i < 32; i += 8)
        t[ty + i][tx] = emb[(size_t)(r0 + ty + i) * DIM + c0 + tx];
    __syncthreads();
    #pragma unroll
    for (int i = 0; i < 32; i += 8) {
        float v = t[tx][ty + i];
        __nv_bfloat16 h = __float2bfloat16(v);
        size_t idx = (size_t)(c0 + ty + i) * NROW + r0 + tx;
        g_Vthi[idx] = h;
        g_Vtlo[idx] = __float2bfloat16(v - __bfloat162float(h));
    }
}

// ---------------------------------------------------------------------------
// Shared GEMM machinery: 128x128 CTA tile, 256 threads (8 warps, 2m x 4n),
// warp tile 64x32, k-chunk 64 (bf16), permuted smem layout, cp.async double
// buffer, mma.sync.m16n8k16 bf16.
// smem per stage: A 16KB + B 16KB; 2 stages = 64KB dynamic.
// ---------------------------------------------------------------------------
#define SMSTAGE 32768

__device__ __forceinline__ void tile_load(const __nv_bfloat16* __restrict__ Asrc,
                                          const __nv_bfloat16* __restrict__ Bsrc,
                                          size_t lda, size_t k0,
                                          int bm0, int bn0, int tid, uint32_t stbase)
{
    uint32_t abase = stbase, bbase = stbase + 16384;
    #pragma unroll
    for (int q = 0; q < 4; q++) {
        int v = tid + q * 256;
        int row = v >> 3, k16 = v & 7;
        uint32_t off = row * 128 + ((k16 ^ (row & 7)) << 4);
        cp16(abase + off, Asrc + (size_t)(bm0 + row) * lda + k0 + k16 * 8);
        cp16(bbase + off, Bsrc + (size_t)(bn0 + row) * lda + k0 + k16 * 8);
    }
    cp_commit();
}

__device__ __forceinline__ void tile_mma(float acc[4][4][4], int lane,
                                         int wm, int wn, uint32_t stbase)
{
    uint32_t abase = stbase, bbase = stbase + 16384;
    #pragma unroll
    for (int kk = 0; kk < 4; kk++) {
        uint32_t a[4][4];
        #pragma unroll
        for (int mi = 0; mi < 4; mi++) {
            int row = wm + mi * 16 + (lane & 15);
            int k16 = 2 * kk + (lane >> 4);
            ldsm4(a[mi][0], a[mi][1], a[mi][2], a[mi][3],
                  abase + row * 128 + ((k16 ^ (row & 7)) << 4));
        }
        #pragma unroll
        for (int jb = 0; jb < 2; jb++) {
            uint32_t b[4];
            int row = wn + jb * 16 + (lane & 7) + ((lane >> 4) << 3);
            int k16 = 2 * kk + ((lane >> 3) & 1);
            ldsm4(b[0], b[1], b[2], b[3],
                  bbase + row * 128 + ((k16 ^ (row & 7)) << 4));
            #pragma unroll
            for (int mi = 0; mi < 4; mi++) {
                mma16816(acc[mi][jb * 2 + 0], a[mi][0], a[mi][1], a[mi][2], a[mi][3], b[0], b[1]);
                mma16816(acc[mi][jb * 2 + 1], a[mi][0], a[mi][1], a[mi][2], a[mi][3], b[2], b[3]);
            }
        }
    }
}

// ---------------------------------------------------------------------------
// K3: W = embn @ embn^T  (split-bf16, K_eff = 3 x 256, 12 chunks of 64).
// ---------------------------------------------------------------------------
__global__ __launch_bounds__(256, 2) void k_gemm_s()
{
    extern __shared__ __align__(128) char dsm[];
    uint32_t dynb = smem_u32(dsm);
    int tid = threadIdx.x, lane = tid & 31, wid = tid >> 5;
    int wm = (wid >> 2) * 64, wn = (wid & 3) * 32;
    int bm0 = blockIdx.y * 128, bn0 = blockIdx.x * 128;

    float acc[4][4][4];
    #pragma unroll
    for (int i = 0; i < 4; i++)
        #pragma unroll
        for (int j = 0; j < 4; j++)
            #pragma unroll
            for (int q = 0; q < 4; q++) acc[i][j][q] = 0.0f;

    const int NIT = 12;   // pass (hi*hi, hi*lo, lo*hi) x 4 chunks
    {
        // it = 0 load
        tile_load(g_Ehi, g_Ehi, DIM, 0, bm0, bn0, tid, dynb);
    }
    for (int it = 0; it < NIT; it++) {
        int s = it & 1;
        int nx = it + 1;
        if (nx < NIT) {
            int pass = nx >> 2, ch = nx & 3;
            const __nv_bfloat16* As = (pass == 2) ? g_Elo : g_Ehi;
            const __nv_bfloat16* Bs = (pass == 1) ? g_Elo : g_Ehi;
            tile_load(As, Bs, DIM, (size_t)ch * 64, bm0, bn0, tid, dynb + (nx & 1) * SMSTAGE);
            cp_wait<1>();
        } else {
            cp_wait<0>();
        }
        __syncthreads();
        tile_mma(acc, lane, wm, wn, dynb + s * SMSTAGE);
        __syncthreads();
    }

    // Epilogue: fp32 W, float2 stores (32B sectors per lane-quad).
    int g = lane >> 2, c2 = (lane & 3) * 2;
    #pragma unroll
    for (int mi = 0; mi < 4; mi++) {
        int r0 = bm0 + wm + mi * 16 + g;
        #pragma unroll
        for (int nj = 0; nj < 4; nj++) {
            int col = bn0 + wn + nj * 8 + c2;
            *(float2*)&g_W[(size_t)r0 * NROW + col]       = make_float2(acc[mi][nj][0], acc[mi][nj][1]);
            *(float2*)&g_W[(size_t)(r0 + 8) * NROW + col] = make_float2(acc[mi][nj][2], acc[mi][nj][3]);
        }
    }
}

// ---------------------------------------------------------------------------
// fast exp on the FMA pipe.
// ---------------------------------------------------------------------------
__device__ __forceinline__ float fast_exp(float x)
{
    float t = x * 1.4426950408889634f;
    t = fmaxf(t, -126.0f);
    float fi = floorf(t);
    float f  = t - fi;
    float p = 1.5403530393381608e-4f;
    p = fmaf(p, f, 1.3333558146428443e-3f);
    p = fmaf(p, f, 9.6181291076284770e-3f);
    p = fmaf(p, f, 5.5504108664821580e-2f);
    p = fmaf(p, f, 2.4022650695910070e-1f);
    p = fmaf(p, f, 6.9314718055994530e-1f);
    p = fmaf(p, f, 1.0f);
    return p * __int_as_float(((int)fi + 127) << 23);
}

// ---------------------------------------------------------------------------
// K4: row softmax on g_W, emit T as bf16 hi/lo.
// ---------------------------------------------------------------------------
__global__ __launch_bounds__(256) void k_softmax()
{
    size_t row = blockIdx.x;
    const float* w = g_W + row * (size_t)NROW;
    int tid = threadIdx.x;
    __shared__ float red[8];

    float4 v[8];
    #pragma unroll
    for (int i = 0; i < 8; i++) v[i] = ((const float4*)w)[tid + i * 256];

    float m = -3.402823466e38f;
    #pragma unroll
    for (int i = 0; i < 8; i++)
        m = fmaxf(m, fmaxf(fmaxf(v[i].x, v[i].y), fmaxf(v[i].z, v[i].w)));
    #pragma unroll
    for (int o = 16; o; o >>= 1) m = fmaxf(m, __shfl_xor_sync(0xFFFFFFFFu, m, o));
    if ((tid & 31) == 0) red[tid >> 5] = m;
    __syncthreads();
    if (tid < 8) {
        float t = red[tid];
        #pragma unroll
        for (int o = 4; o; o >>= 1) t = fmaxf(t, __shfl_xor_sync(0xFFu, t, o));
        if (tid == 0) red[0] = t;
    }
    __syncthreads();
    m = red[0];
    __syncthreads();

    float s = 0.0f;
    #pragma unroll
    for (int i = 0; i < 8; i++) {
        v[i].x = fast_exp(v[i].x - m); v[i].y = fast_exp(v[i].y - m);
        v[i].z = fast_exp(v[i].z - m); v[i].w = fast_exp(v[i].w - m);
        s += (v[i].x + v[i].y) + (v[i].z + v[i].w);
    }
    #pragma unroll
    for (int o = 16; o; o >>= 1) s += __shfl_xor_sync(0xFFFFFFFFu, s, o);
    if ((tid & 31) == 0) red[tid >> 5] = s;
    __syncthreads();
    if (tid < 8) {
        float t = red[tid];
        #pragma unroll
        for (int o = 4; o; o >>= 1) t += __shfl_xor_sync(0xFFu, t, o);
        if (tid == 0) red[0] = t;
    }
    __syncthreads();
    float inv = 1.0f / red[0];

    size_t rbase = row * (size_t)NROW;
    #pragma unroll
    for (int i = 0; i < 8; i++) {
        v[i].x *= inv; v[i].y *= inv; v[i].z *= inv; v[i].w *= inv;
        split4(g_Thi, g_Tlo, rbase + (size_t)(tid + i * 256) * 4, v[i]);
    }
}

// ---------------------------------------------------------------------------
// K5: out = T @ V  (split-bf16, K_eff = 3 x 8192, 384 chunks of 64).
// Grid (2, 64): 128 CTAs; Vt side is L2-resident (8 MB).
// ---------------------------------------------------------------------------
__global__ __launch_bounds__(256, 2) void k_gemm_o(float* __restrict__ C)
{
    extern __shared__ __align__(128) char dsm[];
    uint32_t dynb = smem_u32(dsm);
    int tid = threadIdx.x, lane = tid & 31, wid = tid >> 5;
    int wm = (wid >> 2) * 64, wn = (wid & 3) * 32;
    int bm0 = blockIdx.y * 128, bn0 = blockIdx.x * 128;

    float acc[4][4][4];
    #pragma unroll
    for (int i = 0; i < 4; i++)
        #pragma unroll
        for (int j = 0; j < 4; j++)
            #pragma unroll
            for (int q = 0; q < 4; q++) acc[i][j][q] = 0.0f;

    const int NIT = 384;   // 3 passes x 128 chunks
    tile_load(g_Thi, g_Vthi, NROW, 0, bm0, bn0, tid, dynb);

    #pragma unroll 1
    for (int it = 0; it < NIT; it++) {
        int s = it & 1;
        int nx = it + 1;
        if (nx < NIT) {
            int pass = nx >> 7, ch = nx & 127;
            const __nv_bfloat16* As = (pass == 2) ? g_Tlo  : g_Thi;
            const __nv_bfloat16* Bs = (pass == 1) ? g_Vtlo : g_Vthi;
            tile_load(As, Bs, NROW, (size_t)ch * 64, bm0, bn0, tid, dynb + (nx & 1) * SMSTAGE);
            cp_wait<1>();
        } else {
            cp_wait<0>();
        }
        __syncthreads();
        tile_mma(acc, lane, wm, wn, dynb + s * SMSTAGE);
        __syncthreads();
    }

    int g = lane >> 2, c2 = (lane & 3) * 2;
    #pragma unroll
    for (int mi = 0; mi < 4; mi++) {
        int r0 = bm0 + wm + mi * 16 + g;
        #pragma unroll
        for (int nj = 0; nj < 4; nj++) {
            int col = bn0 + wn + nj * 8 + c2;
            *(float2*)&C[(size_t)r0 * DIM + col]       = make_float2(acc[mi][nj][0], acc[mi][nj][1]);
            *(float2*)&C[(size_t)(r0 + 8) * DIM + col] = make_float2(acc[mi][nj][2], acc[mi][nj][3]);
        }
    }
}

// ---------------------------------------------------------------------------
extern "C" void kernel_launch(void* const* d_in, const int* in_sizes, int n_in,
                              void* d_out, int out_size)
{
    const float* emb = (const float*)d_in[0];
    float* out = (float*)d_out;

    cudaFuncSetAttribute(k_gemm_s, cudaFuncAttributeMaxDynamicSharedMemorySize, 2 * SMSTAGE);
    cudaFuncSetAttribute(k_gemm_o, cudaFuncAttributeMaxDynamicSharedMemorySize, 2 * SMSTAGE);

    k_normalize<<<NROW / 4, 128>>>(emb);

    dim3 tb(32, 8);
    k_transpose_split<<<dim3(NROW / 32, DIM / 32), tb>>>(emb);

    k_gemm_s<<<dim3(NROW / 128, NROW / 128), 256, 2 * SMSTAGE>>>();

    k_softmax<<<NROW, 256>>>();

    k_gemm_o<<<dim3(DIM / 128, NROW / 128), 256, 2 * SMSTAGE>>>(out);
}